// round 3
// baseline (speedup 1.0000x reference)
#include <cuda_runtime.h>
#include <cuda_bf16.h>

typedef unsigned long long u64;

// ---------------- f32x2 packed-math helpers (sm_103a FFMA2) ----------------
__device__ __forceinline__ u64 pack2(float lo, float hi) {
    u64 r;
    asm("mov.b64 %0, {%1, %2};" : "=l"(r)
        : "r"(__float_as_uint(lo)), "r"(__float_as_uint(hi)));
    return r;
}
__device__ __forceinline__ u64 bcast2(float v) { return pack2(v, v); }
__device__ __forceinline__ void fma2(u64& d, u64 a, u64 b) {
    asm("fma.rn.f32x2 %0, %1, %2, %0;" : "+l"(d) : "l"(a), "l"(b));
}
__device__ __forceinline__ float2 unpack2(u64 v) {
    unsigned lo, hi;
    asm("mov.b64 {%0, %1}, %2;" : "=r"(lo), "=r"(hi) : "l"(v));
    return make_float2(__uint_as_float(lo), __uint_as_float(hi));
}

// ---------------- scratch (allocation-free: __device__ globals) ----------------
__device__ float g_a1[64*32*63*63];     // enc1 out
__device__ float g_a2[64*64*32*32];     // enc2 out
__device__ float g_z [64*64*32*32];     // enc3 out (z)
__device__ float g_e [64*64*32*32];     // quantized (q in NCHW)
__device__ float g_d1[64*64*64*64];     // dec1 out
__device__ float g_d2[64*32*128*128];   // dec2 out
__device__ double g_vq_loss;
__device__ double g_recon;

__global__ void k_zero() { g_vq_loss = 0.0; g_recon = 0.0; }

// ---------------- enc conv1: 3->32, k3 s2 p1, 125->63, relu ----------------
__global__ void k_conv1(const float* __restrict__ x, const float* __restrict__ w,
                        const float* __restrict__ b) {
    int idx = blockIdx.x * 256 + threadIdx.x;
    if (idx >= 64*32*63*63) return;
    int ow = idx % 63; int t = idx / 63;
    int oh = t % 63;  t /= 63;
    int co = t % 32;  int n = t / 32;
    float acc = b[co];
    const float* xb = x + n*3*125*125;
    const float* wb = w + co*3*9;
    #pragma unroll
    for (int ci = 0; ci < 3; ci++) {
        #pragma unroll
        for (int kh = 0; kh < 3; kh++) {
            int ih = 2*oh + kh - 1;
            if ((unsigned)ih < 125u) {
                #pragma unroll
                for (int kw = 0; kw < 3; kw++) {
                    int iw = 2*ow + kw - 1;
                    if ((unsigned)iw < 125u)
                        acc += wb[ci*9 + kh*3 + kw] * xb[(ci*125 + ih)*125 + iw];
                }
            }
        }
    }
    g_a1[idx] = fmaxf(acc, 0.f);
}

// ---------------- enc conv2: 32->64, k3 s2 p1, 63->32, relu ------
__global__ void k_conv2(const float* __restrict__ w, const float* __restrict__ b) {
    __shared__ float2 wp[32][4][9];
    int bid  = blockIdx.x;              // 2048 = 64n * 8cog * 4tile
    int tile = bid & 3;
    int cog  = (bid >> 2) & 7;
    int n    = bid >> 5;
    int co0  = cog * 8;
    for (int i = threadIdx.x; i < 32*4*9; i += 256) {
        int t  = i % 9;
        int jp = (i/9) & 3;
        int ci = i / 36;
        wp[ci][jp][t] = make_float2(w[((co0 + 2*jp)    *32 + ci)*9 + t],
                                    w[((co0 + 2*jp + 1)*32 + ci)*9 + t]);
    }
    __syncthreads();
    int px = tile*256 + threadIdx.x;
    int ow = px & 31, oh = px >> 5;
    u64 accp[4];
    #pragma unroll
    for (int jp = 0; jp < 4; jp++) accp[jp] = pack2(b[co0+2*jp], b[co0+2*jp+1]);
    const float* ib = g_a1 + n*32*63*63;
    for (int ci = 0; ci < 32; ci++) {
        u64 in[9];
        #pragma unroll
        for (int kh = 0; kh < 3; kh++) {
            int ih = 2*oh + kh - 1;
            #pragma unroll
            for (int kw = 0; kw < 3; kw++) {
                int iw = 2*ow + kw - 1;
                float v = ((unsigned)ih < 63u && (unsigned)iw < 63u)
                          ? ib[(ci*63 + ih)*63 + iw] : 0.f;
                in[kh*3+kw] = bcast2(v);
            }
        }
        #pragma unroll
        for (int t = 0; t < 9; t++)
            #pragma unroll
            for (int jp = 0; jp < 4; jp++)
                fma2(accp[jp], *(const u64*)&wp[ci][jp][t], in[t]);
    }
    int ohw = oh*32 + ow;
    #pragma unroll
    for (int jp = 0; jp < 4; jp++) {
        float2 v = unpack2(accp[jp]);
        g_a2[(n*64 + co0 + 2*jp    )*1024 + ohw] = fmaxf(v.x, 0.f);
        g_a2[(n*64 + co0 + 2*jp + 1)*1024 + ohw] = fmaxf(v.y, 0.f);
    }
}

// ---------------- enc conv3: 64->64 1x1 (R1 scalar form: fastest measured) --
__global__ void k_conv3(const float* __restrict__ w, const float* __restrict__ b) {
    __shared__ float ws[16*64];
    int bid  = blockIdx.x;                 // 1024 = 64n * 4cog * 4tile
    int tile = bid & 3;
    int cog  = (bid >> 2) & 3;
    int n    = bid >> 4;
    int co0  = cog * 16;
    for (int i = threadIdx.x; i < 1024; i += 256) ws[i] = w[co0*64 + i];
    __syncthreads();
    int hw = tile*256 + threadIdx.x;
    float acc[16];
    #pragma unroll
    for (int j = 0; j < 16; j++) acc[j] = b[co0 + j];
    const float* ib = g_a2 + n*64*1024;
    for (int ci = 0; ci < 64; ci++) {
        float v = ib[ci*1024 + hw];
        #pragma unroll
        for (int j = 0; j < 16; j++) acc[j] += ws[j*64 + ci] * v;
    }
    #pragma unroll
    for (int j = 0; j < 16; j++) g_z[(n*64 + co0 + j)*1024 + hw] = acc[j];
}

// ---------------- VQ: argmin over 512 codes (packed dot) + gather + loss -------
__global__ void k_vq(const float* __restrict__ codebook) {
    __shared__ float4 cbs[128][16];
    __shared__ float  cns[128];
    __shared__ float  wsum[8];
    int n  = blockIdx.x * 256 + threadIdx.x;    // exact: 256 blocks
    int bb = n >> 10;
    int hw = n & 1023;
    const float* zb = g_z + bb*65536 + hw;
    float zv[64];
    #pragma unroll
    for (int d = 0; d < 64; d++) zv[d] = zb[d*1024];
    u64 zp[32];
    #pragma unroll
    for (int q = 0; q < 32; q++) zp[q] = pack2(zv[2*q], zv[2*q+1]);
    float best = 3.0e38f; int bidx = 0;
    for (int c = 0; c < 4; c++) {
        __syncthreads();
        const float4* src = (const float4*)(codebook + c*128*64);
        for (int i = threadIdx.x; i < 2048; i += 256)
            ((float4*)cbs)[i] = src[i];
        __syncthreads();
        if (threadIdx.x < 128) {
            const float* cc = (const float*)cbs[threadIdx.x];
            float s = 0.f;
            #pragma unroll
            for (int d = 0; d < 64; d++) s += cc[d]*cc[d];
            cns[threadIdx.x] = s;
        }
        __syncthreads();
        for (int k = 0; k < 128; k++) {
            const ulonglong2* ck = (const ulonglong2*)cbs[k];
            u64 dotp = 0ull;
            #pragma unroll
            for (int q2 = 0; q2 < 16; q2++) {
                ulonglong2 cv = ck[q2];
                fma2(dotp, cv.x, zp[2*q2]);
                fma2(dotp, cv.y, zp[2*q2+1]);
            }
            float2 dd = unpack2(dotp);
            float dist = cns[k] - 2.f*(dd.x + dd.y);
            if (dist < best) { best = dist; bidx = c*128 + k; }
        }
    }
    const float* cbest = codebook + bidx*64;
    float* eb = g_e + bb*65536 + hw;
    float ls = 0.f;
    #pragma unroll
    for (int d = 0; d < 64; d++) {
        float qv = cbest[d];
        float df = qv - zv[d];
        ls += df*df;
        eb[d*1024] = qv;
    }
    #pragma unroll
    for (int off = 16; off; off >>= 1) ls += __shfl_down_sync(0xffffffffu, ls, off);
    if ((threadIdx.x & 31) == 0) wsum[threadIdx.x >> 5] = ls;
    __syncthreads();
    if (threadIdx.x == 0) {
        float s = 0.f;
        #pragma unroll
        for (int i = 0; i < 8; i++) s += wsum[i];
        atomicAdd(&g_vq_loss, (double)s);
    }
}

// =====================================================================
// decT common core: input tile staged in dynamic smem (17x17 per ci,
// zero-padded), weights packed (co-pairs) in smem, position-major fma2.
//  IN: input NCHW [64ci][S][S]; OUT: [co][2S][2S], co-block of 8 (4 pairs)
// =====================================================================
template<int S>
__device__ __forceinline__ void dec_core(
    const float* __restrict__ ib,   // input base for this n: [64][S][S]
    const float* __restrict__ w,    // weights [64ci][CO][9]
    int CO,                         // total out channels (64 or 32)
    const float* __restrict__ b,
    float* __restrict__ ob,         // output base for this n+co0: [..][2S][2S]
    int co0, int m0, int l0)
{
    extern __shared__ char sdyn[];
    u64*   wp   = (u64*)sdyn;                 // [64][4][9] packed co-pairs
    float* s_in = (float*)(sdyn + 64*4*9*8);  // [64][17][17]

    int tid = threadIdx.x;
    for (int i = tid; i < 64*4*9; i += 256) {
        int t  = i % 9;
        int jp = (i/9) & 3;
        int ci = i / 36;
        ((float2*)wp)[i] = make_float2(w[(ci*CO + co0 + 2*jp    )*9 + t],
                                       w[(ci*CO + co0 + 2*jp + 1)*9 + t]);
    }
    for (int i = tid; i < 64*289; i += 256) {
        int ci = i / 289; int r = i % 289;
        int dm = r / 17, dl = r % 17;
        int m = m0 + dm, l = l0 + dl;
        float v = (m < S && l < S) ? ib[(ci*S + m)*S + l] : 0.f;
        s_in[i] = v;
    }
    __syncthreads();

    int dl = tid & 15, dm = tid >> 4;
    u64 acc[4][4];
    #pragma unroll
    for (int jp = 0; jp < 4; jp++) {
        u64 bv = pack2(b[co0+2*jp], b[co0+2*jp+1]);
        acc[jp][0]=bv; acc[jp][1]=bv; acc[jp][2]=bv; acc[jp][3]=bv;
    }
    const float* sp = s_in + dm*17 + dl;
    #pragma unroll 4
    for (int ci = 0; ci < 64; ci++) {
        const float* p = sp + ci*289;
        u64 P00 = bcast2(p[0]);
        u64 P01 = bcast2(p[1]);
        u64 P10 = bcast2(p[17]);
        u64 P11 = bcast2(p[18]);
        const u64* W = wp + ci*36;
        // position-major: dependent same-acc ops are >=4 apart
        #pragma unroll
        for (int jp = 0; jp < 4; jp++) fma2(acc[jp][0], W[jp*9+4], P00);
        #pragma unroll
        for (int jp = 0; jp < 4; jp++) fma2(acc[jp][1], W[jp*9+3], P01);
        #pragma unroll
        for (int jp = 0; jp < 4; jp++) fma2(acc[jp][1], W[jp*9+5], P00);
        #pragma unroll
        for (int jp = 0; jp < 4; jp++) fma2(acc[jp][2], W[jp*9+1], P10);
        #pragma unroll
        for (int jp = 0; jp < 4; jp++) fma2(acc[jp][2], W[jp*9+7], P00);
        #pragma unroll
        for (int jp = 0; jp < 4; jp++) fma2(acc[jp][3], W[jp*9+0], P11);
        #pragma unroll
        for (int jp = 0; jp < 4; jp++) fma2(acc[jp][3], W[jp*9+2], P10);
        #pragma unroll
        for (int jp = 0; jp < 4; jp++) fma2(acc[jp][3], W[jp*9+6], P01);
        #pragma unroll
        for (int jp = 0; jp < 4; jp++) fma2(acc[jp][3], W[jp*9+8], P00);
    }
    int m = m0 + dm, l = l0 + dl;
    int O = 2*S;
    #pragma unroll
    for (int jp = 0; jp < 4; jp++) {
        float2 a0 = unpack2(acc[jp][0]);
        float2 a1 = unpack2(acc[jp][1]);
        float2 a2 = unpack2(acc[jp][2]);
        float2 a3 = unpack2(acc[jp][3]);
        float* o0 = ob + (2*jp)*O*O + (2*m)*O + 2*l;
        float* o1 = o0 + O*O;
        *(float2*)(o0)     = make_float2(fmaxf(a0.x,0.f), fmaxf(a1.x,0.f));
        *(float2*)(o0 + O) = make_float2(fmaxf(a2.x,0.f), fmaxf(a3.x,0.f));
        *(float2*)(o1)     = make_float2(fmaxf(a0.y,0.f), fmaxf(a1.y,0.f));
        *(float2*)(o1 + O) = make_float2(fmaxf(a2.y,0.f), fmaxf(a3.y,0.f));
    }
}

// decT1: 64->64, in 32x32 -> out 64x64
__global__ void k_dec1(const float* __restrict__ w, const float* __restrict__ b) {
    int bid  = blockIdx.x;             // 2048 = 64n * 8cog * 4quadtile
    int quad = bid & 3;
    int cog  = (bid >> 2) & 7;
    int n    = bid >> 5;
    int co0  = cog * 8;
    int l0 = (quad & 1)*16, m0 = (quad >> 1)*16;
    dec_core<32>(g_e + n*64*1024, w, 64, b, g_d1 + (n*64 + co0)*4096, co0, m0, l0);
}

// decT2: 64->32, in 64x64 -> out 128x128
__global__ void k_dec2(const float* __restrict__ w, const float* __restrict__ b) {
    int bid  = blockIdx.x;             // 4096 = 64n * 4cog * 16tile
    int tile = bid & 15;
    int cog  = (bid >> 4) & 3;
    int n    = bid >> 6;
    int co0  = cog * 8;
    int l0 = (tile & 3)*16, m0 = (tile >> 2)*16;
    dec_core<64>(g_d1 + n*64*4096, w, 32, b, g_d2 + (n*32 + co0)*16384, co0, m0, l0);
}

// ---------------- decT3: 32->3, k2 s1 p2, 128->125 + recon loss -------------
__global__ void k_dec3(const float* __restrict__ w, const float* __restrict__ bs,
                       const float* __restrict__ x, float* __restrict__ out) {
    __shared__ float ws[384];
    __shared__ float wsum[8];
    for (int i = threadIdx.x; i < 384; i += 256) ws[i] = w[i];
    __syncthreads();
    int idx = blockIdx.x * 256 + threadIdx.x;
    float lsum = 0.f;
    if (idx < 1000000) {
        int ow = idx % 125; int t = idx / 125;
        int oh = t % 125;   int n = t / 125;
        u64 accA[3], accB[3];
        #pragma unroll
        for (int co = 0; co < 3; co++) { accA[co] = 0ull; accB[co] = 0ull; }
        const float* ib = g_d2 + n*32*16384;
        const float* p  = ib + (oh+1)*128 + (ow+1);
        const u64* wsu = (const u64*)ws;
        for (int ci = 0; ci < 32; ci++) {
            const float* q = p + ci*16384;
            u64 A = pack2(q[129], q[128]);   // (i22, i21)
            u64 B = pack2(q[1],   q[0]);     // (i12, i11)
            #pragma unroll
            for (int co = 0; co < 3; co++) {
                fma2(accA[co], wsu[ci*6 + co*2    ], A);
                fma2(accB[co], wsu[ci*6 + co*2 + 1], B);
            }
        }
        #pragma unroll
        for (int co = 0; co < 3; co++) {
            float2 a = unpack2(accA[co]);
            float2 c = unpack2(accB[co]);
            float v = bs[co] + a.x + a.y + c.x + c.y;
            int oi = ((n*3 + co)*125 + oh)*125 + ow;
            out[oi] = v;
            float d = v - x[oi];
            lsum += d*d;
        }
    }
    #pragma unroll
    for (int off = 16; off; off >>= 1) lsum += __shfl_down_sync(0xffffffffu, lsum, off);
    if ((threadIdx.x & 31) == 0) wsum[threadIdx.x >> 5] = lsum;
    __syncthreads();
    if (threadIdx.x == 0) {
        float s = 0.f;
        #pragma unroll
        for (int i = 0; i < 8; i++) s += wsum[i];
        atomicAdd(&g_recon, (double)s);
    }
}

// ---------------- finalize: scalars ----------------
__global__ void k_final(float* __restrict__ out) {
    double mse = g_vq_loss / (65536.0 * 64.0);
    float eq  = (float)(1.25 * mse);
    float rec = (float)g_recon;
    out[0] = eq + rec;
    out[1] = eq;
    out[2] = rec;
}

extern "C" void kernel_launch(void* const* d_in, const int* in_sizes, int n_in,
                              void* d_out, int out_size) {
    const float* x   = (const float*)d_in[0];
    const float* ew1 = (const float*)d_in[1];
    const float* eb1 = (const float*)d_in[2];
    const float* ew2 = (const float*)d_in[3];
    const float* eb2 = (const float*)d_in[4];
    const float* ew3 = (const float*)d_in[5];
    const float* eb3 = (const float*)d_in[6];
    const float* cb  = (const float*)d_in[7];
    const float* dw1 = (const float*)d_in[8];
    const float* db1 = (const float*)d_in[9];
    const float* dw2 = (const float*)d_in[10];
    const float* db2 = (const float*)d_in[11];
    const float* dw3 = (const float*)d_in[12];
    const float* db3 = (const float*)d_in[13];
    float* out = (float*)d_out;

    const int DEC_SMEM = 64*4*9*8 + 64*289*4;   // 18432 + 73984 = 92416 B
    static int smem_set = 0;
    if (!smem_set) {
        cudaFuncSetAttribute(k_dec1, cudaFuncAttributeMaxDynamicSharedMemorySize, DEC_SMEM);
        cudaFuncSetAttribute(k_dec2, cudaFuncAttributeMaxDynamicSharedMemorySize, DEC_SMEM);
        smem_set = 1;
    }

    k_zero <<<1, 1>>>();
    k_conv1<<<(64*32*63*63 + 255)/256, 256>>>(x, ew1, eb1);
    k_conv2<<<2048, 256>>>(ew2, eb2);
    k_conv3<<<1024, 256>>>(ew3, eb3);
    k_vq   <<<256, 256>>>(cb);
    k_dec1 <<<2048, 256, DEC_SMEM>>>(dw1, db1);
    k_dec2 <<<4096, 256, DEC_SMEM>>>(dw2, db2);
    k_dec3 <<<3907, 256>>>(dw3, db3, x, out + 3);
    k_final<<<1, 1>>>(out);
}

// round 4
// speedup vs baseline: 1.2742x; 1.2742x over previous
#include <cuda_runtime.h>
#include <cuda_bf16.h>

typedef unsigned long long u64;

// ---------------- f32x2 packed-math helpers (sm_103a FFMA2) ----------------
__device__ __forceinline__ u64 pack2(float lo, float hi) {
    u64 r;
    asm("mov.b64 %0, {%1, %2};" : "=l"(r)
        : "r"(__float_as_uint(lo)), "r"(__float_as_uint(hi)));
    return r;
}
__device__ __forceinline__ u64 bcast2(float v) { return pack2(v, v); }
__device__ __forceinline__ void fma2(u64& d, u64 a, u64 b) {
    asm("fma.rn.f32x2 %0, %1, %2, %0;" : "+l"(d) : "l"(a), "l"(b));
}
__device__ __forceinline__ float2 unpack2(u64 v) {
    unsigned lo, hi;
    asm("mov.b64 {%0, %1}, %2;" : "=r"(lo), "=r"(hi) : "l"(v));
    return make_float2(__uint_as_float(lo), __uint_as_float(hi));
}

// ---------------- scratch (allocation-free: __device__ globals) ----------------
__device__ float g_a1[64*32*63*63];
__device__ float g_a2[64*64*32*32];
__device__ float g_z [64*64*32*32];
__device__ float g_e [64*64*32*32];
__device__ float g_d1[64*64*64*64];
__device__ float g_d2[64*32*128*128];
__device__ double g_vq_loss;
__device__ double g_recon;

__global__ void k_zero() { g_vq_loss = 0.0; g_recon = 0.0; }

// ---------------- enc conv1: 3->32, k3 s2 p1, 125->63, relu ----------------
__global__ void k_conv1(const float* __restrict__ x, const float* __restrict__ w,
                        const float* __restrict__ b) {
    int idx = blockIdx.x * 256 + threadIdx.x;
    if (idx >= 64*32*63*63) return;
    int ow = idx % 63; int t = idx / 63;
    int oh = t % 63;  t /= 63;
    int co = t % 32;  int n = t / 32;
    float acc = b[co];
    const float* xb = x + n*3*125*125;
    const float* wb = w + co*3*9;
    #pragma unroll
    for (int ci = 0; ci < 3; ci++) {
        #pragma unroll
        for (int kh = 0; kh < 3; kh++) {
            int ih = 2*oh + kh - 1;
            if ((unsigned)ih < 125u) {
                #pragma unroll
                for (int kw = 0; kw < 3; kw++) {
                    int iw = 2*ow + kw - 1;
                    if ((unsigned)iw < 125u)
                        acc += wb[ci*9 + kh*3 + kw] * xb[(ci*125 + ih)*125 + iw];
                }
            }
        }
    }
    g_a1[idx] = fmaxf(acc, 0.f);
}

// ---------------- enc conv2: 32->64, k3 s2 p1, 63->32 ------
// co-pair lanes, 2 adjacent-ow pixels per thread share weight loads
__global__ void __launch_bounds__(256) k_conv2(const float* __restrict__ w,
                                               const float* __restrict__ b) {
    __shared__ float2 wp[32][4][9];
    int bid   = blockIdx.x;              // 1024 = 64n * 8cog * 2ohhalf
    int ohh   = bid & 1;
    int cog   = (bid >> 1) & 7;
    int n     = bid >> 4;
    int co0   = cog * 8;
    for (int i = threadIdx.x; i < 32*4*9; i += 256) {
        int t  = i % 9;
        int jp = (i/9) & 3;
        int ci = i / 36;
        wp[ci][jp][t] = make_float2(w[((co0 + 2*jp)    *32 + ci)*9 + t],
                                    w[((co0 + 2*jp + 1)*32 + ci)*9 + t]);
    }
    __syncthreads();
    int q  = threadIdx.x & 15;           // ow pair: ow0 = 2q
    int oh = ohh*16 + (threadIdx.x >> 4);
    u64 accA[4], accB[4];
    #pragma unroll
    for (int jp = 0; jp < 4; jp++) {
        u64 bv = pack2(b[co0+2*jp], b[co0+2*jp+1]);
        accA[jp] = bv; accB[jp] = bv;
    }
    const float* ib = g_a1 + n*32*63*63;
    int iwb = 4*q - 1;
    for (int ci = 0; ci < 32; ci++) {
        u64 col[3][5];
        #pragma unroll
        for (int kh = 0; kh < 3; kh++) {
            int ih = 2*oh + kh - 1;
            bool hok = (unsigned)ih < 63u;
            const float* row = ib + (ci*63 + ih)*63;
            #pragma unroll
            for (int c = 0; c < 5; c++) {
                int iw = iwb + c;
                float v = (hok && (unsigned)iw < 63u) ? row[iw] : 0.f;
                col[kh][c] = bcast2(v);
            }
        }
        #pragma unroll
        for (int kh = 0; kh < 3; kh++) {
            #pragma unroll
            for (int kw = 0; kw < 3; kw++) {
                int t = kh*3 + kw;
                #pragma unroll
                for (int jp = 0; jp < 4; jp++) {
                    u64 W = *(const u64*)&wp[ci][jp][t];
                    fma2(accA[jp], W, col[kh][kw]);
                    fma2(accB[jp], W, col[kh][kw+2]);
                }
            }
        }
    }
    int ohw = oh*32 + 2*q;
    #pragma unroll
    for (int jp = 0; jp < 4; jp++) {
        float2 a = unpack2(accA[jp]);
        float2 c = unpack2(accB[jp]);
        *(float2*)&g_a2[(n*64 + co0 + 2*jp    )*1024 + ohw]
            = make_float2(fmaxf(a.x,0.f), fmaxf(c.x,0.f));
        *(float2*)&g_a2[(n*64 + co0 + 2*jp + 1)*1024 + ohw]
            = make_float2(fmaxf(a.y,0.f), fmaxf(c.y,0.f));
    }
}

// ---------------- enc conv3: 64->64 1x1, pixel-pair lanes --------
__global__ void __launch_bounds__(256) k_conv3(const float* __restrict__ w,
                                               const float* __restrict__ b) {
    __shared__ float2 ws2[16][64];       // duplicated weights (w,w)
    int bid  = blockIdx.x;               // 512 = 64n * 4cog * 2tile
    int tile = bid & 1;
    int cog  = (bid >> 1) & 3;
    int n    = bid >> 3;
    int co0  = cog * 16;
    for (int i = threadIdx.x; i < 1024; i += 256) {
        float v = w[co0*64 + i];
        ws2[i >> 6][i & 63] = make_float2(v, v);
    }
    __syncthreads();
    int base = tile*512 + 2*threadIdx.x;
    u64 acc[16];
    #pragma unroll
    for (int j = 0; j < 16; j++) acc[j] = bcast2(b[co0 + j]);
    const float* ib = g_a2 + n*64*1024;
    for (int ci = 0; ci < 64; ci++) {
        float2 ld = *(const float2*)(ib + ci*1024 + base);
        u64 v = pack2(ld.x, ld.y);
        #pragma unroll
        for (int j = 0; j < 16; j++)
            fma2(acc[j], *(const u64*)&ws2[j][ci], v);
    }
    float* ob = g_z + n*64*1024 + co0*1024 + base;
    #pragma unroll
    for (int j = 0; j < 16; j++) *(u64*)(ob + j*1024) = acc[j];
}

// ---------------- VQ: argmin over 512 codes, 2 codes x even/odd ILP -------
__global__ void k_vq(const float* __restrict__ codebook) {
    __shared__ float4 cbs[128][16];
    __shared__ float  cns[128];
    __shared__ float  wsum[8];
    int n  = blockIdx.x * 256 + threadIdx.x;    // exact: 256 blocks
    int bb = n >> 10;
    int hw = n & 1023;
    const float* zb = g_z + bb*65536 + hw;
    float zv[64];
    #pragma unroll
    for (int d = 0; d < 64; d++) zv[d] = zb[d*1024];
    u64 zp[32];
    #pragma unroll
    for (int q = 0; q < 32; q++) zp[q] = pack2(zv[2*q], zv[2*q+1]);
    float best = 3.0e38f; int bidx = 0;
    for (int c = 0; c < 4; c++) {
        __syncthreads();
        const float4* src = (const float4*)(codebook + c*128*64);
        for (int i = threadIdx.x; i < 2048; i += 256)
            ((float4*)cbs)[i] = src[i];
        __syncthreads();
        if (threadIdx.x < 128) {
            const float* cc = (const float*)cbs[threadIdx.x];
            float s = 0.f;
            #pragma unroll
            for (int d = 0; d < 64; d++) s += cc[d]*cc[d];
            cns[threadIdx.x] = s;
        }
        __syncthreads();
        for (int k = 0; k < 128; k += 2) {
            const ulonglong2* ck0 = (const ulonglong2*)cbs[k];
            const ulonglong2* ck1 = (const ulonglong2*)cbs[k+1];
            u64 d0e = 0ull, d0o = 0ull, d1e = 0ull, d1o = 0ull;
            #pragma unroll
            for (int q2 = 0; q2 < 16; q2++) {
                ulonglong2 c0 = ck0[q2];
                ulonglong2 c1 = ck1[q2];
                fma2(d0e, c0.x, zp[2*q2]);
                fma2(d0o, c0.y, zp[2*q2+1]);
                fma2(d1e, c1.x, zp[2*q2]);
                fma2(d1o, c1.y, zp[2*q2+1]);
            }
            float2 a0 = unpack2(d0e), b0 = unpack2(d0o);
            float2 a1 = unpack2(d1e), b1 = unpack2(d1o);
            float dist0 = cns[k]   - 2.f*(a0.x + a0.y + b0.x + b0.y);
            float dist1 = cns[k+1] - 2.f*(a1.x + a1.y + b1.x + b1.y);
            if (dist0 < best) { best = dist0; bidx = c*128 + k; }
            if (dist1 < best) { best = dist1; bidx = c*128 + k + 1; }
        }
    }
    const float* cbest = codebook + bidx*64;
    float* eb = g_e + bb*65536 + hw;
    float ls = 0.f;
    #pragma unroll
    for (int d = 0; d < 64; d++) {
        float qv = cbest[d];
        float df = qv - zv[d];
        ls += df*df;
        eb[d*1024] = qv;
    }
    #pragma unroll
    for (int off = 16; off; off >>= 1) ls += __shfl_down_sync(0xffffffffu, ls, off);
    if ((threadIdx.x & 31) == 0) wsum[threadIdx.x >> 5] = ls;
    __syncthreads();
    if (threadIdx.x == 0) {
        float s = 0.f;
        #pragma unroll
        for (int i = 0; i < 8; i++) s += wsum[i];
        atomicAdd(&g_vq_loss, (double)s);
    }
}

// =====================================================================
// decT core v2: co-pair lanes, 2 pixels per thread (rows m, m+16)
// share weight LDS. Weights in static smem. Direct LDG inputs (L2-hot).
// =====================================================================
template<int S>
__device__ __forceinline__ void dec_core(
    const float* __restrict__ ib, const float* __restrict__ w, int CO,
    const float* __restrict__ b, float* __restrict__ ob,
    int co0, int m0, int l0)
{
    __shared__ float2 wp[64][4][9];      // 18KB
    int tid = threadIdx.x;
    for (int i = tid; i < 64*4*9; i += 256) {
        int t  = i % 9;
        int jp = (i/9) & 3;
        int ci = i / 36;
        wp[ci][jp][t] = make_float2(w[(ci*CO + co0 + 2*jp    )*9 + t],
                                    w[(ci*CO + co0 + 2*jp + 1)*9 + t]);
    }
    __syncthreads();

    int dl = tid & 15, dm = tid >> 4;
    int l  = l0 + dl;
    int mA = m0 + dm;
    int mB = mA + 16;
    u64 aA[4][4], aB[4][4];
    #pragma unroll
    for (int jp = 0; jp < 4; jp++) {
        u64 bv = pack2(b[co0+2*jp], b[co0+2*jp+1]);
        #pragma unroll
        for (int p = 0; p < 4; p++) { aA[jp][p] = bv; aB[jp][p] = bv; }
    }
    bool lok  = (l  + 1) < S;
    bool mAok = (mA + 1) < S;
    bool mBok = (mB + 1) < S;
    const float* pA0 = ib + mA*S + l;
    const float* pB0 = ib + mB*S + l;
    for (int ci = 0; ci < 64; ci++) {
        const float* pA = pA0 + ci*S*S;
        const float* pB = pB0 + ci*S*S;
        u64 A00 = bcast2(pA[0]);
        u64 A01 = bcast2(lok ? pA[1] : 0.f);
        u64 A10 = bcast2(mAok ? pA[S] : 0.f);
        u64 A11 = bcast2((mAok && lok) ? pA[S+1] : 0.f);
        u64 B00 = bcast2(pB[0]);
        u64 B01 = bcast2(lok ? pB[1] : 0.f);
        u64 B10 = bcast2(mBok ? pB[S] : 0.f);
        u64 B11 = bcast2((mBok && lok) ? pB[S+1] : 0.f);
        #pragma unroll
        for (int jp = 0; jp < 4; jp++) {
            const u64* W = (const u64*)wp[ci][jp];
            u64 w4 = W[4];
            fma2(aA[jp][0], w4, A00); fma2(aB[jp][0], w4, B00);
            u64 w3 = W[3];
            fma2(aA[jp][1], w3, A01); fma2(aB[jp][1], w3, B01);
            u64 w5 = W[5];
            fma2(aA[jp][1], w5, A00); fma2(aB[jp][1], w5, B00);
            u64 w1 = W[1];
            fma2(aA[jp][2], w1, A10); fma2(aB[jp][2], w1, B10);
            u64 w7 = W[7];
            fma2(aA[jp][2], w7, A00); fma2(aB[jp][2], w7, B00);
            u64 w0 = W[0];
            fma2(aA[jp][3], w0, A11); fma2(aB[jp][3], w0, B11);
            u64 w2 = W[2];
            fma2(aA[jp][3], w2, A10); fma2(aB[jp][3], w2, B10);
            u64 w6 = W[6];
            fma2(aA[jp][3], w6, A01); fma2(aB[jp][3], w6, B01);
            u64 w8 = W[8];
            fma2(aA[jp][3], w8, A00); fma2(aB[jp][3], w8, B00);
        }
    }
    const int O = 2*S;
    #pragma unroll
    for (int jp = 0; jp < 4; jp++) {
        float2 a0 = unpack2(aA[jp][0]);
        float2 a1 = unpack2(aA[jp][1]);
        float2 a2 = unpack2(aA[jp][2]);
        float2 a3 = unpack2(aA[jp][3]);
        float* o0 = ob + (2*jp)*O*O + (2*mA)*O + 2*l;
        float* o1 = o0 + O*O;
        *(float2*)(o0)     = make_float2(fmaxf(a0.x,0.f), fmaxf(a1.x,0.f));
        *(float2*)(o0 + O) = make_float2(fmaxf(a2.x,0.f), fmaxf(a3.x,0.f));
        *(float2*)(o1)     = make_float2(fmaxf(a0.y,0.f), fmaxf(a1.y,0.f));
        *(float2*)(o1 + O) = make_float2(fmaxf(a2.y,0.f), fmaxf(a3.y,0.f));
        float2 b0 = unpack2(aB[jp][0]);
        float2 b1 = unpack2(aB[jp][1]);
        float2 b2 = unpack2(aB[jp][2]);
        float2 b3 = unpack2(aB[jp][3]);
        float* q0 = ob + (2*jp)*O*O + (2*mB)*O + 2*l;
        float* q1 = q0 + O*O;
        *(float2*)(q0)     = make_float2(fmaxf(b0.x,0.f), fmaxf(b1.x,0.f));
        *(float2*)(q0 + O) = make_float2(fmaxf(b2.x,0.f), fmaxf(b3.x,0.f));
        *(float2*)(q1)     = make_float2(fmaxf(b0.y,0.f), fmaxf(b1.y,0.f));
        *(float2*)(q1 + O) = make_float2(fmaxf(b2.y,0.f), fmaxf(b3.y,0.f));
    }
}

// decT1: 64->64, 32x32 -> 64x64
__global__ void __launch_bounds__(256, 2) k_dec1(const float* __restrict__ w,
                                                 const float* __restrict__ b) {
    int bid   = blockIdx.x;            // 1024 = 64n * 8cog * 2lhalf
    int lhalf = bid & 1;
    int cog   = (bid >> 1) & 7;
    int n     = bid >> 4;
    int co0   = cog * 8;
    dec_core<32>(g_e + n*64*1024, w, 64, b, g_d1 + (n*64 + co0)*4096,
                 co0, 0, lhalf*16);
}

// decT2: 64->32, 64x64 -> 128x128
__global__ void __launch_bounds__(256, 2) k_dec2(const float* __restrict__ w,
                                                 const float* __restrict__ b) {
    int bid  = blockIdx.x;             // 2048 = 64n * 4cog * 8tile
    int t    = bid & 7;
    int l0   = (t & 3) * 16;
    int m0   = (t >> 2) * 32;
    int cog  = (bid >> 3) & 3;
    int n    = bid >> 5;
    int co0  = cog * 8;
    dec_core<64>(g_d1 + n*64*4096, w, 32, b, g_d2 + (n*32 + co0)*16384,
                 co0, m0, l0);
}

// ---------------- decT3: 32->3, k2 s1 p2, 128->125 + recon loss -------------
__global__ void k_dec3(const float* __restrict__ w, const float* __restrict__ bs,
                       const float* __restrict__ x, float* __restrict__ out) {
    __shared__ float ws[384];
    __shared__ float wsum[8];
    for (int i = threadIdx.x; i < 384; i += 256) ws[i] = w[i];
    __syncthreads();
    int idx = blockIdx.x * 256 + threadIdx.x;
    float lsum = 0.f;
    if (idx < 1000000) {
        int ow = idx % 125; int t = idx / 125;
        int oh = t % 125;   int n = t / 125;
        u64 accA[3], accB[3];
        #pragma unroll
        for (int co = 0; co < 3; co++) { accA[co] = 0ull; accB[co] = 0ull; }
        const float* ib = g_d2 + n*32*16384;
        const float* p  = ib + (oh+1)*128 + (ow+1);
        const u64* wsu = (const u64*)ws;
        for (int ci = 0; ci < 32; ci++) {
            const float* q = p + ci*16384;
            u64 A = pack2(q[129], q[128]);
            u64 B = pack2(q[1],   q[0]);
            #pragma unroll
            for (int co = 0; co < 3; co++) {
                fma2(accA[co], wsu[ci*6 + co*2    ], A);
                fma2(accB[co], wsu[ci*6 + co*2 + 1], B);
            }
        }
        #pragma unroll
        for (int co = 0; co < 3; co++) {
            float2 a = unpack2(accA[co]);
            float2 c = unpack2(accB[co]);
            float v = bs[co] + a.x + a.y + c.x + c.y;
            int oi = ((n*3 + co)*125 + oh)*125 + ow;
            out[oi] = v;
            float d = v - x[oi];
            lsum += d*d;
        }
    }
    #pragma unroll
    for (int off = 16; off; off >>= 1) lsum += __shfl_down_sync(0xffffffffu, lsum, off);
    if ((threadIdx.x & 31) == 0) wsum[threadIdx.x >> 5] = lsum;
    __syncthreads();
    if (threadIdx.x == 0) {
        float s = 0.f;
        #pragma unroll
        for (int i = 0; i < 8; i++) s += wsum[i];
        atomicAdd(&g_recon, (double)s);
    }
}

// ---------------- finalize ----------------
__global__ void k_final(float* __restrict__ out) {
    double mse = g_vq_loss / (65536.0 * 64.0);
    float eq  = (float)(1.25 * mse);
    float rec = (float)g_recon;
    out[0] = eq + rec;
    out[1] = eq;
    out[2] = rec;
}

extern "C" void kernel_launch(void* const* d_in, const int* in_sizes, int n_in,
                              void* d_out, int out_size) {
    const float* x   = (const float*)d_in[0];
    const float* ew1 = (const float*)d_in[1];
    const float* eb1 = (const float*)d_in[2];
    const float* ew2 = (const float*)d_in[3];
    const float* eb2 = (const float*)d_in[4];
    const float* ew3 = (const float*)d_in[5];
    const float* eb3 = (const float*)d_in[6];
    const float* cb  = (const float*)d_in[7];
    const float* dw1 = (const float*)d_in[8];
    const float* db1 = (const float*)d_in[9];
    const float* dw2 = (const float*)d_in[10];
    const float* db2 = (const float*)d_in[11];
    const float* dw3 = (const float*)d_in[12];
    const float* db3 = (const float*)d_in[13];
    float* out = (float*)d_out;

    k_zero <<<1, 1>>>();
    k_conv1<<<(64*32*63*63 + 255)/256, 256>>>(x, ew1, eb1);
    k_conv2<<<1024, 256>>>(ew2, eb2);
    k_conv3<<<512, 256>>>(ew3, eb3);
    k_vq   <<<256, 256>>>(cb);
    k_dec1 <<<1024, 256>>>(dw1, db1);
    k_dec2 <<<2048, 256>>>(dw2, db2);
    k_dec3 <<<3907, 256>>>(dw3, db3, x, out + 3);
    k_final<<<1, 1>>>(out);
}